// round 9
// baseline (speedup 1.0000x reference)
#include <cuda_runtime.h>
#include <cstdint>

#define NPTS  100000
#define KVOL  27
#define PAIRS 60000
#define CCH   64
#define TP    256
#define NTILES ((PAIRS + TP - 1) / TP)

// smem: sA 256x64 tf32 (swizzled 256B rows, 64KB) | sB 64x64 tf32 (16KB) | maps
// W-transpose scratch (64x66 f32 = 16.9KB) transiently occupies the sA region.
#define SA_OFF   0
#define SB_OFF   65536
#define MAPS_OFF 81920
#define SMEM_BYTES 83968

#define RED_V4(ptr, x, y, z, w) \
    asm volatile("red.global.add.v4.f32 [%0], {%1,%2,%3,%4};" \
                 :: "l"(ptr), "f"(x), "f"(y), "f"(z), "f"(w) : "memory")

__device__ __forceinline__ uint32_t smem_u32(const void* p) {
    uint32_t a;
    asm("{ .reg .u64 t; cvta.to.shared.u64 t, %1; cvt.u32.u64 %0, t; }"
        : "=r"(a) : "l"(p));
    return a;
}

__device__ __forceinline__ uint32_t f2tf32(float f) {
    uint32_t r;
    asm("cvt.rna.tf32.f32 %0, %1;" : "=r"(r) : "f"(f));
    return r;
}

#define LDSM_X4(r0, r1, r2, r3, addr) \
    asm volatile("ldmatrix.sync.aligned.m8n8.x4.shared.b16 {%0,%1,%2,%3}, [%4];" \
                 : "=r"(r0), "=r"(r1), "=r"(r2), "=r"(r3) : "r"(addr))

#define MMA_TF32(c, a0, a1, a2, a3, b0, b1) \
    asm volatile("mma.sync.aligned.m16n8k8.row.col.f32.tf32.tf32.f32 " \
                 "{%0,%1,%2,%3}, {%4,%5,%6,%7}, {%8,%9}, {%0,%1,%2,%3};" \
                 : "+f"(c[0]), "+f"(c[1]), "+f"(c[2]), "+f"(c[3]) \
                 : "r"(a0), "r"(a1), "r"(a2), "r"(a3), "r"(b0), "r"(b1))

__global__ void __launch_bounds__(256) init_bias_kernel(
    const float* __restrict__ bias, float* __restrict__ out)
{
    int idx = blockIdx.x * 256 + threadIdx.x;
    if (idx < NPTS * CCH) out[idx] = bias[idx & (CCH - 1)];
}

// swizzled byte offset inside a 256B row: chunk' = k16 ^ (row & 7)
__device__ __forceinline__ uint32_t sw_off(int row, int k16) {
    return (uint32_t)(row * 256 + ((k16 ^ (row & 7)) << 4));
}

__global__ void __launch_bounds__(256, 2) sparse_conv_kernel(
    const float* __restrict__ input,
    const float* __restrict__ kernel,
    const int*   __restrict__ in_map,
    const int*   __restrict__ out_map,
    float*       __restrict__ out)
{
    extern __shared__ __align__(1024) char smem[];
    const uint32_t sb = smem_u32(smem);
    int* sIn  = (int*)(smem + MAPS_OFF);
    int* sOut = sIn + TP;

    const int k    = blockIdx.y;
    const int base = blockIdx.x * TP;
    const int tid  = threadIdx.x;
    const int w    = tid >> 5;
    const int l    = tid & 31;
    const int nrem = min(TP, PAIRS - base);

    // pair maps (coalesced, 256 threads = 256 pairs)
    if (tid < nrem) {
        sIn[tid]  = in_map [k * PAIRS + base + tid];
        sOut[tid] = out_map[k * PAIRS + base + tid];
    } else {
        sIn[tid] = -1;
        sOut[tid] = -1;
    }

    // ---- W phase 1: coalesced LDG of W_k, store to padded scratch [i][n]
    // (stride 66 floats; write is 2-way at worst, read is conflict-free) ----
    {
        const float4* Wg = (const float4*)(kernel + k * CCH * CCH);
        float4 wv[4];
        #pragma unroll
        for (int s = 0; s < 4; s++) wv[s] = Wg[tid + 256 * s];
        float* scratch = (float*)smem;
        #pragma unroll
        for (int s = 0; s < 4; s++) {
            int e  = tid + 256 * s;          // float4 index in [0,1024)
            int i  = e >> 4;                 // K row
            int o4 = e & 15;                 // n-group of 4
            float* d = scratch + 66 * i + 4 * o4;
            d[0] = wv[s].x; d[1] = wv[s].y; d[2] = wv[s].z; d[3] = wv[s].w;
        }
    }
    __syncthreads();                          // maps + scratch visible

    // ---- W phase 2: transposed read (conflict-free), tf32 cvt,
    // swizzled STS.128 into sB rows (n-major over K) ----
    {
        float* scratch = (float*)smem;
        int n  = tid & 63;
        int ib = (tid >> 6) * 16;             // 16 K-values per thread
        uint32_t tv[16];
        #pragma unroll
        for (int j = 0; j < 16; j++) tv[j] = f2tf32(scratch[66 * (ib + j) + n]);
        #pragma unroll
        for (int c = 0; c < 4; c++) {
            uint4 q = make_uint4(tv[4*c], tv[4*c+1], tv[4*c+2], tv[4*c+3]);
            *(uint4*)(smem + SB_OFF + sw_off(n, (ib >> 2) + c)) = q;
        }
    }
    __syncthreads();                          // scratch reads done; sA now free

    // ---- gather X -> sA (tf32, swizzled). 16 lanes per row: coalesced 256B
    // gmem reads, conflict-free STS.128 ----
    #pragma unroll
    for (int s = 0; s < 16; s++) {
        int m   = tid + 256 * s;
        int p   = m >> 4;                     // pair row 0..255
        int j16 = m & 15;
        int row = sIn[p];
        float4 v = make_float4(0.f, 0.f, 0.f, 0.f);
        if (row >= 0) v = ((const float4*)input)[row * (CCH / 4) + j16];
        uint4 t;
        t.x = f2tf32(v.x); t.y = f2tf32(v.y);
        t.z = f2tf32(v.z); t.w = f2tf32(v.w);
        *(uint4*)(smem + SA_OFF + sw_off(p, j16)) = t;
    }
    __syncthreads();

    // ---- GEMM: warp w computes rows [32w, 32w+32) x all 64 cols ----
    float acc[2][8][4];
    #pragma unroll
    for (int mt = 0; mt < 2; mt++)
        #pragma unroll
        for (int nt = 0; nt < 8; nt++)
            #pragma unroll
            for (int c = 0; c < 4; c++) acc[mt][nt][c] = 0.f;

    const int arow = 32 * w + (((l >> 3) & 1) << 3) + (l & 7);  // + 16*mt
    const int ahi  = l >> 4;
    const int asw  = arow & 7;
    const int brow = ((l >> 4) << 3) + (l & 7);                 // + n0
    const int bhi  = (l >> 3) & 1;
    const int bsw  = brow & 7;
    const uint32_t aBase = sb + SA_OFF + arow * 256;
    const uint32_t bBase = sb + SB_OFF + brow * 256;

    #pragma unroll
    for (int kk = 0; kk < 8; kk++) {
        uint32_t a[2][4];
        #pragma unroll
        for (int mt = 0; mt < 2; mt++) {
            uint32_t addr = aBase + mt * 4096 + ((((kk << 1) | ahi) ^ asw) << 4);
            LDSM_X4(a[mt][0], a[mt][1], a[mt][2], a[mt][3], addr);
        }
        uint32_t b[8][2];
        #pragma unroll
        for (int g = 0; g < 4; g++) {          // n0 = 16g
            uint32_t r0, r1, r2, r3;
            uint32_t addr = bBase + g * 4096 + ((((kk << 1) | bhi) ^ bsw) << 4);
            LDSM_X4(r0, r1, r2, r3, addr);
            b[2 * g][0] = r0;     b[2 * g][1] = r1;
            b[2 * g + 1][0] = r2; b[2 * g + 1][1] = r3;
        }
        #pragma unroll
        for (int mt = 0; mt < 2; mt++)
            #pragma unroll
            for (int nt = 0; nt < 8; nt++)
                MMA_TF32(acc[mt][nt], a[mt][0], a[mt][1], a[mt][2], a[mt][3],
                         b[nt][0], b[nt][1]);
    }

    // ---- scatter-add: butterfly shfl (l^1) -> one guarded red.v4 per (mt,nt) ----
    const int odd = l & 1;
    #pragma unroll
    for (int mt = 0; mt < 2; mt++) {
        int row = 32 * w + 16 * mt + (l >> 2) + (odd ? 8 : 0);
        int o   = sOut[row];
        int cb  = 2 * (l & 3) - (odd ? 2 : 0);
        #pragma unroll
        for (int nt = 0; nt < 8; nt++) {
            float s0 = odd ? acc[mt][nt][0] : acc[mt][nt][2];
            float s1 = odd ? acc[mt][nt][1] : acc[mt][nt][3];
            float r0 = __shfl_xor_sync(0xffffffffu, s0, 1);
            float r1 = __shfl_xor_sync(0xffffffffu, s1, 1);
            float v0 = odd ? r0 : acc[mt][nt][0];
            float v1 = odd ? r1 : acc[mt][nt][1];
            float v2 = odd ? acc[mt][nt][2] : r0;
            float v3 = odd ? acc[mt][nt][3] : r1;
            if (o >= 0)
                RED_V4(out + o * CCH + 8 * nt + cb, v0, v1, v2, v3);
        }
    }
}

extern "C" void kernel_launch(void* const* d_in, const int* in_sizes, int n_in,
                              void* d_out, int out_size)
{
    const float* input  = (const float*)d_in[0];
    const float* kern   = (const float*)d_in[1];
    const float* bias   = (const float*)d_in[2];
    const int*   in_map = (const int*)  d_in[3];
    const int*   out_map= (const int*)  d_in[4];
    float* out = (float*)d_out;

    cudaFuncSetAttribute(sparse_conv_kernel,
                         cudaFuncAttributeMaxDynamicSharedMemorySize, SMEM_BYTES);

    init_bias_kernel<<<(NPTS * CCH + 255) / 256, 256>>>(bias, out);

    dim3 grid(NTILES, KVOL);
    sparse_conv_kernel<<<grid, 256, SMEM_BYTES>>>(input, kern, in_map, out_map, out);
}

// round 10
// speedup vs baseline: 1.2456x; 1.2456x over previous
#include <cuda_runtime.h>
#include <cstdint>

#define NPTS  100000
#define KVOL  27
#define PAIRS 60000
#define CCH   64
#define TP    256
#define NTILES ((PAIRS + TP - 1) / TP)

// smem: sA 256x64 f32-as-tf32 (swizzled 256B rows, 64KB) | sB 64x64 tf32 (16KB)
//       | W transpose scratch 64x66 f32 (16.9KB). No map staging (register+shfl).
#define SA_OFF   0
#define SB_OFF   65536
#define WS_OFF   81920
#define SMEM_BYTES 98816

#define RED_V4(ptr, x, y, z, w) \
    asm volatile("red.global.add.v4.f32 [%0], {%1,%2,%3,%4};" \
                 :: "l"(ptr), "f"(x), "f"(y), "f"(z), "f"(w) : "memory")

__device__ __forceinline__ uint32_t smem_u32(const void* p) {
    uint32_t a;
    asm("{ .reg .u64 t; cvta.to.shared.u64 t, %1; cvt.u32.u64 %0, t; }"
        : "=r"(a) : "l"(p));
    return a;
}

__device__ __forceinline__ uint32_t f2tf32(float f) {
    uint32_t r;
    asm("cvt.rna.tf32.f32 %0, %1;" : "=r"(r) : "f"(f));
    return r;
}

#define CP_ASYNC16(dst, src, sz) \
    asm volatile("cp.async.ca.shared.global [%0], [%1], 16, %2;" \
                 :: "r"(dst), "l"(src), "r"(sz) : "memory")

#define LDSM_X4(r0, r1, r2, r3, addr) \
    asm volatile("ldmatrix.sync.aligned.m8n8.x4.shared.b16 {%0,%1,%2,%3}, [%4];" \
                 : "=r"(r0), "=r"(r1), "=r"(r2), "=r"(r3) : "r"(addr))

#define MMA_TF32(c, a0, a1, a2, a3, b0, b1) \
    asm volatile("mma.sync.aligned.m16n8k8.row.col.f32.tf32.tf32.f32 " \
                 "{%0,%1,%2,%3}, {%4,%5,%6,%7}, {%8,%9}, {%0,%1,%2,%3};" \
                 : "+f"(c[0]), "+f"(c[1]), "+f"(c[2]), "+f"(c[3]) \
                 : "r"(a0), "r"(a1), "r"(a2), "r"(a3), "r"(b0), "r"(b1))

__global__ void __launch_bounds__(256) init_bias_kernel(
    const float* __restrict__ bias, float* __restrict__ out)
{
    int idx = blockIdx.x * 256 + threadIdx.x;
    if (idx < NPTS * CCH) out[idx] = bias[idx & (CCH - 1)];
}

// swizzled byte offset inside a 256B row: chunk' = k16 ^ (row & 7)
__device__ __forceinline__ uint32_t sw_off(int row, int k16) {
    return (uint32_t)(row * 256 + ((k16 ^ (row & 7)) << 4));
}

__global__ void __launch_bounds__(256, 2) sparse_conv_kernel(
    const float* __restrict__ input,
    const float* __restrict__ kernel,
    const int*   __restrict__ in_map,
    const int*   __restrict__ out_map,
    float*       __restrict__ out)
{
    extern __shared__ __align__(1024) char smem[];
    const uint32_t sb = smem_u32(smem);

    const int k    = blockIdx.y;
    const int base = blockIdx.x * TP;
    const int tid  = threadIdx.x;
    const int w    = tid >> 5;
    const int l    = tid & 31;
    const int nrem = min(TP, PAIRS - base);

    // per-lane maps (registers only; warp w owns pair rows 32w..32w+31)
    int myIn = -1, myOut = -1;
    if (tid < nrem) {
        myIn  = in_map [k * PAIRS + base + tid];
        myOut = out_map[k * PAIRS + base + tid];
    }

    // W LDG early (independent of maps; overlaps the map-load latency)
    float4 wv[4];
    {
        const float4* Wg = (const float4*)(kernel + k * CCH * CCH);
        #pragma unroll
        for (int s = 0; s < 4; s++) wv[s] = Wg[tid + 256 * s];
    }

    // ---- gather via cp.async: warp-local rows, 16 lanes per row ->
    // coalesced 256B gmem reads, direct gmem->smem, zero-fill for tail ----
    #pragma unroll
    for (int s = 0; s < 16; s++) {
        int rsel = 2 * s + (l >> 4);              // row-in-warp 0..31
        int row  = __shfl_sync(0xffffffffu, myIn, rsel);
        int p    = 32 * w + rsel;
        int j16  = l & 15;
        uint32_t dst = sb + SA_OFF + sw_off(p, j16);
        const char* src = (const char*)input
                        + (size_t)(row < 0 ? 0 : row) * 256 + j16 * 16;
        unsigned sz = (row >= 0) ? 16u : 0u;
        CP_ASYNC16(dst, src, sz);
    }
    asm volatile("cp.async.commit_group;" ::: "memory");

    // ---- W phase 1: store to padded scratch [i][n] (stride 66 floats) ----
    {
        float* scratch = (float*)(smem + WS_OFF);
        #pragma unroll
        for (int s = 0; s < 4; s++) {
            int e  = tid + 256 * s;               // float4 index in [0,1024)
            int i  = e >> 4;                      // K row
            int o4 = e & 15;                      // n-group of 4
            float* d = scratch + 66 * i + 4 * o4;
            d[0] = wv[s].x; d[1] = wv[s].y; d[2] = wv[s].z; d[3] = wv[s].w;
        }
    }
    __syncthreads();                              // scratch visible

    // ---- W phase 2: transposed conflict-free read, tf32 cvt, swizzled STS ----
    {
        float* scratch = (float*)(smem + WS_OFF);
        int n  = tid & 63;
        int ib = (tid >> 6) * 16;                 // 16 K-values per thread
        uint32_t tv[16];
        #pragma unroll
        for (int j = 0; j < 16; j++) tv[j] = f2tf32(scratch[66 * (ib + j) + n]);
        #pragma unroll
        for (int c = 0; c < 4; c++) {
            uint4 q = make_uint4(tv[4*c], tv[4*c+1], tv[4*c+2], tv[4*c+3]);
            *(uint4*)(smem + SB_OFF + sw_off(n, (ib >> 2) + c)) = q;
        }
    }
    asm volatile("cp.async.wait_group 0;" ::: "memory");
    __syncthreads();                              // sA + sB ready

    // ---- GEMM: warp w computes rows [32w, 32w+32) x all 64 cols ----
    float acc[2][8][4];
    #pragma unroll
    for (int mt = 0; mt < 2; mt++)
        #pragma unroll
        for (int nt = 0; nt < 8; nt++)
            #pragma unroll
            for (int c = 0; c < 4; c++) acc[mt][nt][c] = 0.f;

    const int arow = 32 * w + (((l >> 3) & 1) << 3) + (l & 7);  // + 16*mt
    const int ahi  = l >> 4;
    const int asw  = arow & 7;
    const int brow = ((l >> 4) << 3) + (l & 7);                 // + n0
    const int bhi  = (l >> 3) & 1;
    const int bsw  = brow & 7;
    const uint32_t aBase = sb + SA_OFF + arow * 256;
    const uint32_t bBase = sb + SB_OFF + brow * 256;

    #pragma unroll
    for (int kk = 0; kk < 8; kk++) {
        uint32_t a[2][4];
        #pragma unroll
        for (int mt = 0; mt < 2; mt++) {
            uint32_t addr = aBase + mt * 4096 + ((((kk << 1) | ahi) ^ asw) << 4);
            LDSM_X4(a[mt][0], a[mt][1], a[mt][2], a[mt][3], addr);
        }
        uint32_t b[8][2];
        #pragma unroll
        for (int g = 0; g < 4; g++) {             // n0 = 16g
            uint32_t r0, r1, r2, r3;
            uint32_t addr = bBase + g * 4096 + ((((kk << 1) | bhi) ^ bsw) << 4);
            LDSM_X4(r0, r1, r2, r3, addr);
            b[2 * g][0] = r0;     b[2 * g][1] = r1;
            b[2 * g + 1][0] = r2; b[2 * g + 1][1] = r3;
        }
        #pragma unroll
        for (int mt = 0; mt < 2; mt++)
            #pragma unroll
            for (int nt = 0; nt < 8; nt++)
                MMA_TF32(acc[mt][nt], a[mt][0], a[mt][1], a[mt][2], a[mt][3],
                         b[nt][0], b[nt][1]);
    }

    // ---- scatter-add: butterfly shfl (l^1) -> one guarded red.v4 per (mt,nt);
    // output row comes from warp-local shfl of myOut ----
    const int odd = l & 1;
    #pragma unroll
    for (int mt = 0; mt < 2; mt++) {
        int rsel = 16 * mt + (l >> 2) + (odd ? 8 : 0);   // row-in-warp 0..31
        int o    = __shfl_sync(0xffffffffu, myOut, rsel);
        int cb   = 2 * (l & 3) - (odd ? 2 : 0);
        #pragma unroll
        for (int nt = 0; nt < 8; nt++) {
            float s0 = odd ? acc[mt][nt][0] : acc[mt][nt][2];
            float s1 = odd ? acc[mt][nt][1] : acc[mt][nt][3];
            float r0 = __shfl_xor_sync(0xffffffffu, s0, 1);
            float r1 = __shfl_xor_sync(0xffffffffu, s1, 1);
            float v0 = odd ? r0 : acc[mt][nt][0];
            float v1 = odd ? r1 : acc[mt][nt][1];
            float v2 = odd ? acc[mt][nt][2] : r0;
            float v3 = odd ? acc[mt][nt][3] : r1;
            if (o >= 0)
                RED_V4(out + o * CCH + 8 * nt + cb, v0, v1, v2, v3);
        }
    }
}

extern "C" void kernel_launch(void* const* d_in, const int* in_sizes, int n_in,
                              void* d_out, int out_size)
{
    const float* input  = (const float*)d_in[0];
    const float* kern   = (const float*)d_in[1];
    const float* bias   = (const float*)d_in[2];
    const int*   in_map = (const int*)  d_in[3];
    const int*   out_map= (const int*)  d_in[4];
    float* out = (float*)d_out;

    cudaFuncSetAttribute(sparse_conv_kernel,
                         cudaFuncAttributeMaxDynamicSharedMemorySize, SMEM_BYTES);

    init_bias_kernel<<<(NPTS * CCH + 255) / 256, 256>>>(bias, out);

    dim3 grid(NTILES, KVOL);
    sparse_conv_kernel<<<grid, 256, SMEM_BYTES>>>(input, kern, in_map, out_map, out);
}

// round 11
// speedup vs baseline: 1.2736x; 1.0225x over previous
#include <cuda_runtime.h>
#include <cstdint>

#define NPTS  100000
#define KVOL  27
#define PAIRS 60000
#define CCH   64
#define RPT   128                      // pair rows per tile
#define TPB   8                        // tiles per block
#define NT128 ((PAIRS + RPT - 1) / RPT)        // 469
#define GX    ((NT128 + TPB - 1) / TPB)        // 59

// smem: sA[2] 128x64 f32-as-tf32 (swizzled 256B rows, 2x32KB) | sB 64x64 tf32
//       (16KB) | W scratch 64x66 f32 (16.9KB) | maps: 3 bufs x (128 in + 128 out)
#define SA_OFF   0
#define SB_OFF   65536
#define WS_OFF   81920
#define MAPS_OFF 98816
#define SMEM_BYTES 101888

#define RED_V4(ptr, x, y, z, w) \
    asm volatile("red.global.add.v4.f32 [%0], {%1,%2,%3,%4};" \
                 :: "l"(ptr), "f"(x), "f"(y), "f"(z), "f"(w) : "memory")

__device__ __forceinline__ uint32_t smem_u32(const void* p) {
    uint32_t a;
    asm("{ .reg .u64 t; cvta.to.shared.u64 t, %1; cvt.u32.u64 %0, t; }"
        : "=r"(a) : "l"(p));
    return a;
}

__device__ __forceinline__ uint32_t f2tf32(float f) {
    uint32_t r;
    asm("cvt.rna.tf32.f32 %0, %1;" : "=r"(r) : "f"(f));
    return r;
}

#define CP_ASYNC16(dst, src, sz) \
    asm volatile("cp.async.ca.shared.global [%0], [%1], 16, %2;" \
                 :: "r"(dst), "l"(src), "r"(sz) : "memory")

#define LDSM_X4(r0, r1, r2, r3, addr) \
    asm volatile("ldmatrix.sync.aligned.m8n8.x4.shared.b16 {%0,%1,%2,%3}, [%4];" \
                 : "=r"(r0), "=r"(r1), "=r"(r2), "=r"(r3) : "r"(addr))

#define MMA_TF32(c, a0, a1, a2, a3, b0, b1) \
    asm volatile("mma.sync.aligned.m16n8k8.row.col.f32.tf32.tf32.f32 " \
                 "{%0,%1,%2,%3}, {%4,%5,%6,%7}, {%8,%9}, {%0,%1,%2,%3};" \
                 : "+f"(c[0]), "+f"(c[1]), "+f"(c[2]), "+f"(c[3]) \
                 : "r"(a0), "r"(a1), "r"(a2), "r"(a3), "r"(b0), "r"(b1))

__global__ void __launch_bounds__(256) init_bias_kernel(
    const float* __restrict__ bias, float* __restrict__ out)
{
    int idx = blockIdx.x * 256 + threadIdx.x;
    if (idx < NPTS * CCH) out[idx] = bias[idx & (CCH - 1)];
}

// swizzled byte offset inside a 256B row: chunk' = k16 ^ (row & 7)
__device__ __forceinline__ uint32_t sw_off(int row, int k16) {
    return (uint32_t)(row * 256 + ((k16 ^ (row & 7)) << 4));
}

__global__ void __launch_bounds__(256, 2) sparse_conv_kernel(
    const float* __restrict__ input,
    const float* __restrict__ kernel,
    const int*   __restrict__ in_map,
    const int*   __restrict__ out_map,
    float*       __restrict__ out)
{
    extern __shared__ __align__(1024) char smem[];
    const uint32_t sb = smem_u32(smem);
    int* mapsB = (int*)(smem + MAPS_OFF);   // 3 bufs x 256 ints (in[128], out[128])

    const int k    = blockIdx.y;
    const int t0   = blockIdx.x * TPB;      // first 128-pair tile of this block
    const int tid  = threadIdx.x;
    const int w    = tid >> 5;
    const int l    = tid & 31;
    const int band = w >> 1;                // 32-row band
    const int half = w & 1;                 // 32-col half

    // ---- prologue: W LDG + maps(tile0) LDG issued together ----
    float4 wv[4];
    {
        const float4* Wg = (const float4*)(kernel + k * CCH * CCH);
        #pragma unroll
        for (int s = 0; s < 4; s++) wv[s] = Wg[tid + 256 * s];
    }
    int mIn = -1, mOut = -1;
    if (tid < RPT) {
        int pp = t0 * RPT + tid;
        if (pp < PAIRS) {
            mIn  = in_map [k * PAIRS + pp];
            mOut = out_map[k * PAIRS + pp];
        }
    }

    // W -> padded scratch [i][n] (stride 66); maps tile0 -> buf 0
    {
        float* scratch = (float*)(smem + WS_OFF);
        #pragma unroll
        for (int s = 0; s < 4; s++) {
            int e  = tid + 256 * s;
            int i  = e >> 4;
            int o4 = e & 15;
            float* d = scratch + 66 * i + 4 * o4;
            d[0] = wv[s].x; d[1] = wv[s].y; d[2] = wv[s].z; d[3] = wv[s].w;
        }
    }
    if (tid < RPT) {
        mapsB[tid]       = mIn;
        mapsB[RPT + tid] = mOut;
    }
    __syncthreads();

    // issue gather for tile 0 (maps via LDS), then W transpose -> sB
    #pragma unroll
    for (int s = 0; s < 8; s++) {
        int m   = tid + 256 * s;
        int p   = m >> 4;
        int j16 = m & 15;
        int row = mapsB[p];
        uint32_t dst = sb + SA_OFF + sw_off(p, j16);
        const char* src = (const char*)input
                        + (size_t)(row < 0 ? 0 : row) * 256 + j16 * 16;
        CP_ASYNC16(dst, src, row >= 0 ? 16u : 0u);
    }
    asm volatile("cp.async.commit_group;" ::: "memory");

    {
        float* scratch = (float*)(smem + WS_OFF);
        int n  = tid & 63;
        int ib = (tid >> 6) * 16;
        uint32_t tv[16];
        #pragma unroll
        for (int j = 0; j < 16; j++) tv[j] = f2tf32(scratch[66 * (ib + j) + n]);
        #pragma unroll
        for (int c = 0; c < 4; c++) {
            uint4 q = make_uint4(tv[4*c], tv[4*c+1], tv[4*c+2], tv[4*c+3]);
            *(uint4*)(smem + SB_OFF + sw_off(n, (ib >> 2) + c)) = q;
        }
    }

    // LDG maps for tile 1
    mIn = -1; mOut = -1;
    if (tid < RPT && 1 < TPB) {
        int pp = (t0 + 1) * RPT + tid;
        if (pp < PAIRS) {
            mIn  = in_map [k * PAIRS + pp];
            mOut = out_map[k * PAIRS + pp];
        }
    }

    // GEMM fragment constants
    const int arowB = 32 * band + (((l >> 3) & 1) << 3) + (l & 7);  // + 16*mt
    const int ahi   = l >> 4;
    const int asw   = arowB & 7;
    const int brow  = ((l >> 4) << 3) + (l & 7);                    // + n0
    const int bhi   = (l >> 3) & 1;
    const int bsw   = brow & 7;
    const uint32_t bBase = sb + SB_OFF + brow * 256;
    const int odd = l & 1;

    // ---- pipelined tile loop ----
    for (int t = 0; t < TPB; t++) {
        const int cur = t & 1;
        const int mb  = t % 3;
        const int nb  = (t + 1) % 3;

        asm volatile("cp.async.wait_group 0;" ::: "memory");

        // stage maps for tile t+1 (regs loaded last iteration)
        if (t + 1 < TPB && tid < RPT) {
            mapsB[nb * 256 + tid]       = mIn;
            mapsB[nb * 256 + RPT + tid] = mOut;
        }
        __syncthreads();   // sA[cur] data ready; maps t+1 visible; sA[cur^1] reads (tile t-1) done

        // issue gather for tile t+1 into the other buffer
        if (t + 1 < TPB) {
            #pragma unroll
            for (int s = 0; s < 8; s++) {
                int m   = tid + 256 * s;
                int p   = m >> 4;
                int j16 = m & 15;
                int row = mapsB[nb * 256 + p];
                uint32_t dst = sb + SA_OFF + (cur ^ 1) * 32768 + sw_off(p, j16);
                const char* src = (const char*)input
                                + (size_t)(row < 0 ? 0 : row) * 256 + j16 * 16;
                CP_ASYNC16(dst, src, row >= 0 ? 16u : 0u);
            }
            asm volatile("cp.async.commit_group;" ::: "memory");
            // LDG maps for tile t+2
            mIn = -1; mOut = -1;
            if (t + 2 < TPB && tid < RPT) {
                int pp = (t0 + t + 2) * RPT + tid;
                if (pp < PAIRS) {
                    mIn  = in_map [k * PAIRS + pp];
                    mOut = out_map[k * PAIRS + pp];
                }
            }
        }

        // ---- GEMM: warp (band,half) -> rows [32*band,+32) x cols [32*half,+32) ----
        float acc[2][4][4];
        #pragma unroll
        for (int mt = 0; mt < 2; mt++)
            #pragma unroll
            for (int nt = 0; nt < 4; nt++)
                #pragma unroll
                for (int c = 0; c < 4; c++) acc[mt][nt][c] = 0.f;

        const uint32_t aBase = sb + SA_OFF + cur * 32768 + arowB * 256;

        #pragma unroll
        for (int kk = 0; kk < 8; kk++) {
            uint32_t a[2][4];
            #pragma unroll
            for (int mt = 0; mt < 2; mt++) {
                uint32_t addr = aBase + mt * 4096 + ((((kk << 1) | ahi) ^ asw) << 4);
                LDSM_X4(a[mt][0], a[mt][1], a[mt][2], a[mt][3], addr);
            }
            uint32_t b[4][2];
            #pragma unroll
            for (int gl = 0; gl < 2; gl++) {
                int g = 2 * half + gl;
                uint32_t r0, r1, r2, r3;
                uint32_t addr = bBase + g * 4096 + ((((kk << 1) | bhi) ^ bsw) << 4);
                LDSM_X4(r0, r1, r2, r3, addr);
                b[2 * gl][0] = r0;     b[2 * gl][1] = r1;
                b[2 * gl + 1][0] = r2; b[2 * gl + 1][1] = r3;
            }
            #pragma unroll
            for (int mt = 0; mt < 2; mt++)
                #pragma unroll
                for (int nt = 0; nt < 4; nt++)
                    MMA_TF32(acc[mt][nt], a[mt][0], a[mt][1], a[mt][2], a[mt][3],
                             b[nt][0], b[nt][1]);
        }

        // ---- scatter: butterfly shfl -> one guarded red.v4 per (mt,nt) ----
        const int* sOutB = mapsB + mb * 256 + RPT;
        #pragma unroll
        for (int mt = 0; mt < 2; mt++) {
            int row = 32 * band + 16 * mt + (l >> 2) + (odd ? 8 : 0);
            int o   = sOutB[row];
            int cb  = 2 * (l & 3) - (odd ? 2 : 0);
            #pragma unroll
            for (int nt = 0; nt < 4; nt++) {
                float s0 = odd ? acc[mt][nt][0] : acc[mt][nt][2];
                float s1 = odd ? acc[mt][nt][1] : acc[mt][nt][3];
                float r0 = __shfl_xor_sync(0xffffffffu, s0, 1);
                float r1 = __shfl_xor_sync(0xffffffffu, s1, 1);
                float v0 = odd ? r0 : acc[mt][nt][0];
                float v1 = odd ? r1 : acc[mt][nt][1];
                float v2 = odd ? acc[mt][nt][2] : r0;
                float v3 = odd ? acc[mt][nt][3] : r1;
                if (o >= 0)
                    RED_V4(out + o * CCH + 8 * (4 * half + nt) + cb, v0, v1, v2, v3);
            }
        }
    }
}

extern "C" void kernel_launch(void* const* d_in, const int* in_sizes, int n_in,
                              void* d_out, int out_size)
{
    const float* input  = (const float*)d_in[0];
    const float* kern   = (const float*)d_in[1];
    const float* bias   = (const float*)d_in[2];
    const int*   in_map = (const int*)  d_in[3];
    const int*   out_map= (const int*)  d_in[4];
    float* out = (float*)d_out;

    cudaFuncSetAttribute(sparse_conv_kernel,
                         cudaFuncAttributeMaxDynamicSharedMemorySize, SMEM_BYTES);

    init_bias_kernel<<<(NPTS * CCH + 255) / 256, 256>>>(bias, out);

    dim3 grid(GX, KVOL);
    sparse_conv_kernel<<<grid, 256, SMEM_BYTES>>>(input, kern, in_map, out_map, out);
}

// round 12
// speedup vs baseline: 1.3824x; 1.0854x over previous
#include <cuda_runtime.h>
#include <cstdint>

#define NPTS  100000
#define KVOL  27
#define PAIRS 60000
#define CCH   64
#define RPT   128                      // pair rows per tile
#define TPB   8                        // tiles per block
#define NT128 ((PAIRS + RPT - 1) / RPT)        // 469
#define GX    ((NT128 + TPB - 1) / TPB)        // 59

// smem: sA[2] 128x64 f32-as-tf32 (swizzled 256B rows, 2x32KB) | sB 64x64 tf32
//       (16KB) | W scratch 64x66 f32 (16.9KB) | maps: 3 bufs x (128 in + 128 out)
#define SA_OFF   0
#define SB_OFF   65536
#define WS_OFF   81920
#define MAPS_OFF 98816
#define SMEM_BYTES 101888

#define RED_V4(ptr, x, y, z, w) \
    asm volatile("red.global.add.v4.f32 [%0], {%1,%2,%3,%4};" \
                 :: "l"(ptr), "f"(x), "f"(y), "f"(z), "f"(w) : "memory")

__device__ __forceinline__ uint32_t smem_u32(const void* p) {
    uint32_t a;
    asm("{ .reg .u64 t; cvta.to.shared.u64 t, %1; cvt.u32.u64 %0, t; }"
        : "=r"(a) : "l"(p));
    return a;
}

__device__ __forceinline__ uint32_t f2tf32(float f) {
    uint32_t r;
    asm("cvt.rna.tf32.f32 %0, %1;" : "=r"(r) : "f"(f));
    return r;
}

#define CP_ASYNC16(dst, src, sz) \
    asm volatile("cp.async.ca.shared.global [%0], [%1], 16, %2;" \
                 :: "r"(dst), "l"(src), "r"(sz) : "memory")

#define LDSM_X4(r0, r1, r2, r3, addr) \
    asm volatile("ldmatrix.sync.aligned.m8n8.x4.shared.b16 {%0,%1,%2,%3}, [%4];" \
                 : "=r"(r0), "=r"(r1), "=r"(r2), "=r"(r3) : "r"(addr))

#define MMA_TF32(c, a0, a1, a2, a3, b0, b1) \
    asm volatile("mma.sync.aligned.m16n8k8.row.col.f32.tf32.tf32.f32 " \
                 "{%0,%1,%2,%3}, {%4,%5,%6,%7}, {%8,%9}, {%0,%1,%2,%3};" \
                 : "+f"(c[0]), "+f"(c[1]), "+f"(c[2]), "+f"(c[3]) \
                 : "r"(a0), "r"(a1), "r"(a2), "r"(a3), "r"(b0), "r"(b1))

__global__ void __launch_bounds__(256) init_bias_kernel(
    const float* __restrict__ bias, float* __restrict__ out)
{
    int idx = blockIdx.x * 256 + threadIdx.x;
    if (idx < NPTS * CCH) out[idx] = bias[idx & (CCH - 1)];
}

// swizzled byte offset inside a 256B row: chunk' = k16 ^ (row & 7)
__device__ __forceinline__ uint32_t sw_off(int row, int k16) {
    return (uint32_t)(row * 256 + ((k16 ^ (row & 7)) << 4));
}

__global__ void __launch_bounds__(256, 2) sparse_conv_kernel(
    const float* __restrict__ input,
    const float* __restrict__ kernel,
    const int*   __restrict__ in_map,
    const int*   __restrict__ out_map,
    float*       __restrict__ out)
{
    extern __shared__ __align__(1024) char smem[];
    const uint32_t sb = smem_u32(smem);
    int* mapsB = (int*)(smem + MAPS_OFF);   // 3 bufs x 256 ints (in[128], out[128])

    const int k    = blockIdx.y;
    const int t0   = blockIdx.x * TPB;      // first 128-pair tile of this block
    const int tid  = threadIdx.x;
    const int w    = tid >> 5;
    const int l    = tid & 31;
    const int band = w >> 1;                // 32-row band
    const int half = w & 1;                 // 32-col half

    // ---- prologue: W LDG + maps(tile0) LDG issued together ----
    float4 wv[4];
    {
        const float4* Wg = (const float4*)(kernel + k * CCH * CCH);
        #pragma unroll
        for (int s = 0; s < 4; s++) wv[s] = Wg[tid + 256 * s];
    }
    int mIn = -1, mOut = -1;
    if (tid < RPT) {
        int pp = t0 * RPT + tid;
        if (pp < PAIRS) {
            mIn  = in_map [k * PAIRS + pp];
            mOut = out_map[k * PAIRS + pp];
        }
    }

    // W -> padded scratch [i][n] (stride 66); maps tile0 -> buf 0
    {
        float* scratch = (float*)(smem + WS_OFF);
        #pragma unroll
        for (int s = 0; s < 4; s++) {
            int e  = tid + 256 * s;
            int i  = e >> 4;
            int o4 = e & 15;
            float* d = scratch + 66 * i + 4 * o4;
            d[0] = wv[s].x; d[1] = wv[s].y; d[2] = wv[s].z; d[3] = wv[s].w;
        }
    }
    if (tid < RPT) {
        mapsB[tid]       = mIn;
        mapsB[RPT + tid] = mOut;
    }
    __syncthreads();

    // issue gather for tile 0 (maps via LDS), then W transpose -> sB
    #pragma unroll
    for (int s = 0; s < 8; s++) {
        int m   = tid + 256 * s;
        int p   = m >> 4;
        int j16 = m & 15;
        int row = mapsB[p];
        uint32_t dst = sb + SA_OFF + sw_off(p, j16);
        const char* src = (const char*)input
                        + (size_t)(row < 0 ? 0 : row) * 256 + j16 * 16;
        CP_ASYNC16(dst, src, row >= 0 ? 16u : 0u);
    }
    asm volatile("cp.async.commit_group;" ::: "memory");

    {
        float* scratch = (float*)(smem + WS_OFF);
        int n  = tid & 63;
        int ib = (tid >> 6) * 16;
        uint32_t tv[16];
        #pragma unroll
        for (int j = 0; j < 16; j++) tv[j] = f2tf32(scratch[66 * (ib + j) + n]);
        #pragma unroll
        for (int c = 0; c < 4; c++) {
            uint4 q = make_uint4(tv[4*c], tv[4*c+1], tv[4*c+2], tv[4*c+3]);
            *(uint4*)(smem + SB_OFF + sw_off(n, (ib >> 2) + c)) = q;
        }
    }

    // LDG maps for tile 1
    mIn = -1; mOut = -1;
    if (tid < RPT && 1 < TPB) {
        int pp = (t0 + 1) * RPT + tid;
        if (pp < PAIRS) {
            mIn  = in_map [k * PAIRS + pp];
            mOut = out_map[k * PAIRS + pp];
        }
    }

    // GEMM fragment constants
    const int arowB = 32 * band + (((l >> 3) & 1) << 3) + (l & 7);  // + 16*mt
    const int ahi   = l >> 4;
    const int asw   = arowB & 7;
    const int brow  = ((l >> 4) << 3) + (l & 7);                    // + n0
    const int bhi   = (l >> 3) & 1;
    const int bsw   = brow & 7;
    const uint32_t bBase = sb + SB_OFF + brow * 256;
    const int Q = l >> 2;
    const int q = l & 3;

    // ---- pipelined tile loop ----
    for (int t = 0; t < TPB; t++) {
        const int cur = t & 1;
        const int mb  = t % 3;
        const int nb  = (t + 1) % 3;

        asm volatile("cp.async.wait_group 0;" ::: "memory");

        // stage maps for tile t+1 (regs loaded last iteration)
        if (t + 1 < TPB && tid < RPT) {
            mapsB[nb * 256 + tid]       = mIn;
            mapsB[nb * 256 + RPT + tid] = mOut;
        }
        __syncthreads();   // sA[cur] data ready; maps t+1 visible; sA[cur^1] reads (tile t-1) done

        // issue gather for tile t+1 into the other buffer
        if (t + 1 < TPB) {
            #pragma unroll
            for (int s = 0; s < 8; s++) {
                int m   = tid + 256 * s;
                int p   = m >> 4;
                int j16 = m & 15;
                int row = mapsB[nb * 256 + p];
                uint32_t dst = sb + SA_OFF + (cur ^ 1) * 32768 + sw_off(p, j16);
                const char* src = (const char*)input
                                + (size_t)(row < 0 ? 0 : row) * 256 + j16 * 16;
                CP_ASYNC16(dst, src, row >= 0 ? 16u : 0u);
            }
            asm volatile("cp.async.commit_group;" ::: "memory");
            // LDG maps for tile t+2
            mIn = -1; mOut = -1;
            if (t + 2 < TPB && tid < RPT) {
                int pp = (t0 + t + 2) * RPT + tid;
                if (pp < PAIRS) {
                    mIn  = in_map [k * PAIRS + pp];
                    mOut = out_map[k * PAIRS + pp];
                }
            }
        }

        // ---- GEMM: warp (band,half) -> rows [32*band,+32) x cols [32*half,+32) ----
        float acc[2][4][4];
        #pragma unroll
        for (int mt = 0; mt < 2; mt++)
            #pragma unroll
            for (int nt = 0; nt < 4; nt++)
                #pragma unroll
                for (int c = 0; c < 4; c++) acc[mt][nt][c] = 0.f;

        const uint32_t aBase = sb + SA_OFF + cur * 32768 + arowB * 256;

        #pragma unroll
        for (int kk = 0; kk < 8; kk++) {
            uint32_t a[2][4];
            #pragma unroll
            for (int mt = 0; mt < 2; mt++) {
                uint32_t addr = aBase + mt * 4096 + ((((kk << 1) | ahi) ^ asw) << 4);
                LDSM_X4(a[mt][0], a[mt][1], a[mt][2], a[mt][3], addr);
            }
            uint32_t b[4][2];
            #pragma unroll
            for (int gl = 0; gl < 2; gl++) {
                int g = 2 * half + gl;
                uint32_t r0, r1, r2, r3;
                uint32_t addr = bBase + g * 4096 + ((((kk << 1) | bhi) ^ bsw) << 4);
                LDSM_X4(r0, r1, r2, r3, addr);
                b[2 * gl][0] = r0;     b[2 * gl][1] = r1;
                b[2 * gl + 1][0] = r2; b[2 * gl + 1][1] = r3;
            }
            #pragma unroll
            for (int mt = 0; mt < 2; mt++)
                #pragma unroll
                for (int nt = 0; nt < 4; nt++)
                    MMA_TF32(acc[mt][nt], a[mt][0], a[mt][1], a[mt][2], a[mt][3],
                             b[nt][0], b[nt][1]);
        }

        // ---- scatter: intra-quad regroup so each quad holds 4 consecutive
        // 16B chunks of ONE row -> each red.v4 inst touches 8 rows (not 16).
        // target lane (q): cols 32*half + 16*x + 4q + j of row (Q, h);
        // source: acc[mt][2x + (q>>1)][2h + (j&1)] of quad-lane 2(q&1)+(j>>1).
        const int* sOutB = mapsB + mb * 256 + RPT;
        #pragma unroll
        for (int mt = 0; mt < 2; mt++) {
            #pragma unroll
            for (int h = 0; h < 2; h++) {
                int row = 32 * band + 16 * mt + Q + 8 * h;
                int o   = sOutB[row];
                #pragma unroll
                for (int x = 0; x < 2; x++) {
                    float v[4];
                    #pragma unroll
                    for (int j = 0; j < 4; j++) {
                        int par  = j & 1;
                        int srcl = (l & ~3) + 2 * (q & 1) + (j >> 1);
                        float s0 = __shfl_sync(0xffffffffu,
                                               acc[mt][2 * x + 0][2 * h + par], srcl);
                        float s1 = __shfl_sync(0xffffffffu,
                                               acc[mt][2 * x + 1][2 * h + par], srcl);
                        v[j] = (q >> 1) ? s1 : s0;
                    }
                    if (o >= 0)
                        RED_V4(out + o * CCH + 32 * half + 16 * x + 4 * q,
                               v[0], v[1], v[2], v[3]);
                }
            }
        }
    }
}

extern "C" void kernel_launch(void* const* d_in, const int* in_sizes, int n_in,
                              void* d_out, int out_size)
{
    const float* input  = (const float*)d_in[0];
    const float* kern   = (const float*)d_in[1];
    const float* bias   = (const float*)d_in[2];
    const int*   in_map = (const int*)  d_in[3];
    const int*   out_map= (const int*)  d_in[4];
    float* out = (float*)d_out;

    cudaFuncSetAttribute(sparse_conv_kernel,
                         cudaFuncAttributeMaxDynamicSharedMemorySize, SMEM_BYTES);

    init_bias_kernel<<<(NPTS * CCH + 255) / 256, 256>>>(bias, out);

    dim3 grid(GX, KVOL);
    sparse_conv_kernel<<<grid, 256, SMEM_BYTES>>>(input, kern, in_map, out_map, out);
}

// round 13
// speedup vs baseline: 1.4940x; 1.0807x over previous
#include <cuda_runtime.h>
#include <cstdint>

#define NPTS  100000
#define KVOL  27
#define PAIRS 60000
#define CCH   64
#define RPT   128                      // pair rows per tile
#define TPB   8                        // tiles per block
#define NT128 ((PAIRS + RPT - 1) / RPT)        // 469
#define GX    ((NT128 + TPB - 1) / TPB)        // 59

// smem: sA[2] 128x64 f32-as-tf32 (swizzled 256B rows, 2x32KB) | sB 64x64 tf32
//       (16KB) | W scratch 64x66 f32 (16.9KB) | maps: 3 bufs x (128 in + 128 out)
#define SA_OFF   0
#define SB_OFF   65536
#define WS_OFF   81920
#define MAPS_OFF 98816
#define SMEM_BYTES 101888

#define RED_V4(ptr, x, y, z, w) \
    asm volatile("red.global.add.v4.f32 [%0], {%1,%2,%3,%4};" \
                 :: "l"(ptr), "f"(x), "f"(y), "f"(z), "f"(w) : "memory")

__device__ __forceinline__ uint32_t smem_u32(const void* p) {
    uint32_t a;
    asm("{ .reg .u64 t; cvta.to.shared.u64 t, %1; cvt.u32.u64 %0, t; }"
        : "=r"(a) : "l"(p));
    return a;
}

__device__ __forceinline__ uint32_t f2tf32(float f) {
    uint32_t r;
    asm("cvt.rna.tf32.f32 %0, %1;" : "=r"(r) : "f"(f));
    return r;
}

#define CP_ASYNC16(dst, src, sz) \
    asm volatile("cp.async.ca.shared.global [%0], [%1], 16, %2;" \
                 :: "r"(dst), "l"(src), "r"(sz) : "memory")

#define LDSM_X4(r0, r1, r2, r3, addr) \
    asm volatile("ldmatrix.sync.aligned.m8n8.x4.shared.b16 {%0,%1,%2,%3}, [%4];" \
                 : "=r"(r0), "=r"(r1), "=r"(r2), "=r"(r3) : "r"(addr))

#define MMA_TF32(c, a0, a1, a2, a3, b0, b1) \
    asm volatile("mma.sync.aligned.m16n8k8.row.col.f32.tf32.tf32.f32 " \
                 "{%0,%1,%2,%3}, {%4,%5,%6,%7}, {%8,%9}, {%0,%1,%2,%3};" \
                 : "+f"(c[0]), "+f"(c[1]), "+f"(c[2]), "+f"(c[3]) \
                 : "r"(a0), "r"(a1), "r"(a2), "r"(a3), "r"(b0), "r"(b1))

__global__ void __launch_bounds__(256) init_bias_kernel(
    const float* __restrict__ bias, float* __restrict__ out)
{
    int idx = blockIdx.x * 256 + threadIdx.x;
    if (idx < NPTS * CCH) out[idx] = bias[idx & (CCH - 1)];
}

// swizzled byte offset inside a 256B row: chunk' = k16 ^ (row & 7)
__device__ __forceinline__ uint32_t sw_off(int row, int k16) {
    return (uint32_t)(row * 256 + ((k16 ^ (row & 7)) << 4));
}

__global__ void __launch_bounds__(256) sparse_conv_kernel(
    const float* __restrict__ input,
    const float* __restrict__ kernel,
    const int*   __restrict__ in_map,
    const int*   __restrict__ out_map,
    float*       __restrict__ out)
{
    extern __shared__ __align__(1024) char smem[];
    const uint32_t sb = smem_u32(smem);
    int* mapsB = (int*)(smem + MAPS_OFF);   // 3 bufs x 256 ints (in[128], out[128])

    const int k    = blockIdx.y;
    const int t0   = blockIdx.x * TPB;      // first 128-pair tile of this block
    const int tid  = threadIdx.x;
    const int w    = tid >> 5;
    const int l    = tid & 31;
    const int band = w >> 1;                // 32-row band
    const int half = w & 1;                 // 32-col half

    // ---- prologue: W LDG + maps(tile0) LDG issued together ----
    float4 wv[4];
    {
        const float4* Wg = (const float4*)(kernel + k * CCH * CCH);
        #pragma unroll
        for (int s = 0; s < 4; s++) wv[s] = Wg[tid + 256 * s];
    }
    int mIn = -1, mOut = -1;
    if (tid < RPT) {
        int pp = t0 * RPT + tid;
        if (pp < PAIRS) {
            mIn  = in_map [k * PAIRS + pp];
            mOut = out_map[k * PAIRS + pp];
        }
    }

    // W -> padded scratch [i][n] (stride 66); maps tile0 -> buf 0
    {
        float* scratch = (float*)(smem + WS_OFF);
        #pragma unroll
        for (int s = 0; s < 4; s++) {
            int e  = tid + 256 * s;
            int i  = e >> 4;
            int o4 = e & 15;
            float* d = scratch + 66 * i + 4 * o4;
            d[0] = wv[s].x; d[1] = wv[s].y; d[2] = wv[s].z; d[3] = wv[s].w;
        }
    }
    if (tid < RPT) {
        mapsB[tid]       = mIn;
        mapsB[RPT + tid] = mOut;
    }
    __syncthreads();

    // issue gather for tile 0 (maps via LDS), then W transpose -> sB
    #pragma unroll
    for (int s = 0; s < 8; s++) {
        int m   = tid + 256 * s;
        int p   = m >> 4;
        int j16 = m & 15;
        int row = mapsB[p];
        uint32_t dst = sb + SA_OFF + sw_off(p, j16);
        const char* src = (const char*)input
                        + (size_t)(row < 0 ? 0 : row) * 256 + j16 * 16;
        CP_ASYNC16(dst, src, row >= 0 ? 16u : 0u);
    }
    asm volatile("cp.async.commit_group;" ::: "memory");

    {
        float* scratch = (float*)(smem + WS_OFF);
        int n  = tid & 63;
        int ib = (tid >> 6) * 16;
        uint32_t tv[16];
        #pragma unroll
        for (int j = 0; j < 16; j++) tv[j] = f2tf32(scratch[66 * (ib + j) + n]);
        #pragma unroll
        for (int c = 0; c < 4; c++) {
            uint4 q = make_uint4(tv[4*c], tv[4*c+1], tv[4*c+2], tv[4*c+3]);
            *(uint4*)(smem + SB_OFF + sw_off(n, (ib >> 2) + c)) = q;
        }
    }

    // LDG maps for tile 1
    mIn = -1; mOut = -1;
    if (tid < RPT && 1 < TPB) {
        int pp = (t0 + 1) * RPT + tid;
        if (pp < PAIRS) {
            mIn  = in_map [k * PAIRS + pp];
            mOut = out_map[k * PAIRS + pp];
        }
    }

    // GEMM fragment constants
    const int arowB = 32 * band + (((l >> 3) & 1) << 3) + (l & 7);  // + 16*mt
    const int ahi   = l >> 4;
    const int asw   = arowB & 7;
    const int brow  = ((l >> 4) << 3) + (l & 7);                    // + n0
    const int bhi   = (l >> 3) & 1;
    const int bsw   = brow & 7;
    const uint32_t bBase = sb + SB_OFF + brow * 256;
    const int Q = l >> 2;
    const int q = l & 3;

    // ---- hoist ALL B fragments into registers (sB is block-constant):
    // per-tile B-LDSM vanishes from the tile loop ----
    __syncthreads();                        // sB fully written, block-wide
    uint32_t bf[8][4][2];
    #pragma unroll
    for (int kk = 0; kk < 8; kk++) {
        #pragma unroll
        for (int gl = 0; gl < 2; gl++) {
            int g = 2 * half + gl;
            uint32_t r0, r1, r2, r3;
            uint32_t addr = bBase + g * 4096 + ((((kk << 1) | bhi) ^ bsw) << 4);
            LDSM_X4(r0, r1, r2, r3, addr);
            bf[kk][2 * gl][0] = r0;     bf[kk][2 * gl][1] = r1;
            bf[kk][2 * gl + 1][0] = r2; bf[kk][2 * gl + 1][1] = r3;
        }
    }

    // ---- pipelined tile loop ----
    for (int t = 0; t < TPB; t++) {
        const int cur = t & 1;
        const int mb  = t % 3;
        const int nb  = (t + 1) % 3;

        asm volatile("cp.async.wait_group 0;" ::: "memory");

        // stage maps for tile t+1 (regs loaded last iteration)
        if (t + 1 < TPB && tid < RPT) {
            mapsB[nb * 256 + tid]       = mIn;
            mapsB[nb * 256 + RPT + tid] = mOut;
        }
        __syncthreads();   // sA[cur] ready; maps t+1 visible; sA[cur^1] reads done

        // issue gather for tile t+1 into the other buffer
        if (t + 1 < TPB) {
            #pragma unroll
            for (int s = 0; s < 8; s++) {
                int m   = tid + 256 * s;
                int p   = m >> 4;
                int j16 = m & 15;
                int row = mapsB[nb * 256 + p];
                uint32_t dst = sb + SA_OFF + (cur ^ 1) * 32768 + sw_off(p, j16);
                const char* src = (const char*)input
                                + (size_t)(row < 0 ? 0 : row) * 256 + j16 * 16;
                CP_ASYNC16(dst, src, row >= 0 ? 16u : 0u);
            }
            asm volatile("cp.async.commit_group;" ::: "memory");
            // LDG maps for tile t+2
            mIn = -1; mOut = -1;
            if (t + 2 < TPB && tid < RPT) {
                int pp = (t0 + t + 2) * RPT + tid;
                if (pp < PAIRS) {
                    mIn  = in_map [k * PAIRS + pp];
                    mOut = out_map[k * PAIRS + pp];
                }
            }
        }

        // ---- GEMM: warp (band,half) -> rows [32*band,+32) x cols [32*half,+32) ----
        float acc[2][4][4];
        #pragma unroll
        for (int mt = 0; mt < 2; mt++)
            #pragma unroll
            for (int nt = 0; nt < 4; nt++)
                #pragma unroll
                for (int c = 0; c < 4; c++) acc[mt][nt][c] = 0.f;

        const uint32_t aBase = sb + SA_OFF + cur * 32768 + arowB * 256;

        #pragma unroll
        for (int kk = 0; kk < 8; kk++) {
            uint32_t a[2][4];
            #pragma unroll
            for (int mt = 0; mt < 2; mt++) {
                uint32_t addr = aBase + mt * 4096 + ((((kk << 1) | ahi) ^ asw) << 4);
                LDSM_X4(a[mt][0], a[mt][1], a[mt][2], a[mt][3], addr);
            }
            #pragma unroll
            for (int mt = 0; mt < 2; mt++)
                #pragma unroll
                for (int nt = 0; nt < 4; nt++)
                    MMA_TF32(acc[mt][nt], a[mt][0], a[mt][1], a[mt][2], a[mt][3],
                             bf[kk][nt][0], bf[kk][nt][1]);
        }

        // ---- scatter: intra-quad regroup -> each red.v4 touches 8 rows ----
        const int* sOutB = mapsB + mb * 256 + RPT;
        #pragma unroll
        for (int mt = 0; mt < 2; mt++) {
            #pragma unroll
            for (int h = 0; h < 2; h++) {
                int row = 32 * band + 16 * mt + Q + 8 * h;
                int o   = sOutB[row];
                #pragma unroll
                for (int x = 0; x < 2; x++) {
                    float v[4];
                    #pragma unroll
                    for (int j = 0; j < 4; j++) {
                        int par  = j & 1;
                        int srcl = (l & ~3) + 2 * (q & 1) + (j >> 1);
                        float s0 = __shfl_sync(0xffffffffu,
                                               acc[mt][2 * x + 0][2 * h + par], srcl);
                        float s1 = __shfl_sync(0xffffffffu,
                                               acc[mt][2 * x + 1][2 * h + par], srcl);
                        v[j] = (q >> 1) ? s1 : s0;
                    }
                    if (o >= 0)
                        RED_V4(out + o * CCH + 32 * half + 16 * x + 4 * q,
                               v[0], v[1], v[2], v[3]);
                }
            }
        }
    }
}

extern "C" void kernel_launch(void* const* d_in, const int* in_sizes, int n_in,
                              void* d_out, int out_size)
{
    const float* input  = (const float*)d_in[0];
    const float* kern   = (const float*)d_in[1];
    const float* bias   = (const float*)d_in[2];
    const int*   in_map = (const int*)  d_in[3];
    const int*   out_map= (const int*)  d_in[4];
    float* out = (float*)d_out;

    cudaFuncSetAttribute(sparse_conv_kernel,
                         cudaFuncAttributeMaxDynamicSharedMemorySize, SMEM_BYTES);

    init_bias_kernel<<<(NPTS * CCH + 255) / 256, 256>>>(bias, out);

    dim3 grid(GX, KVOL);
    sparse_conv_kernel<<<grid, 256, SMEM_BYTES>>>(input, kern, in_map, out_map, out);
}

// round 14
// speedup vs baseline: 1.6616x; 1.1121x over previous
#include <cuda_runtime.h>
#include <cstdint>

#define NPTS  100000
#define KVOL  27
#define PAIRS 60000
#define CCH   64
#define RPT   128                      // pair rows per tile
#define TPB   8                        // tiles per block
#define NT128 ((PAIRS + RPT - 1) / RPT)        // 469
#define GX    ((NT128 + TPB - 1) / TPB)        // 59

// smem: sA[2] 128x64 f32-as-tf32 (swizzled 256B rows, 2x32KB) | sB 64x64 tf32
//       (16KB) | W scratch 64x66 f32 (16.9KB) | maps: 3 bufs x (128 in + 128 out)
#define SA_OFF   0
#define SB_OFF   65536
#define WS_OFF   81920
#define MAPS_OFF 98816
#define SMEM_BYTES 101888

#define RED_V4(ptr, x, y, z, w) \
    asm volatile("red.global.add.v4.f32 [%0], {%1,%2,%3,%4};" \
                 :: "l"(ptr), "f"(x), "f"(y), "f"(z), "f"(w) : "memory")

__device__ __forceinline__ uint32_t smem_u32(const void* p) {
    uint32_t a;
    asm("{ .reg .u64 t; cvta.to.shared.u64 t, %1; cvt.u32.u64 %0, t; }"
        : "=r"(a) : "l"(p));
    return a;
}

__device__ __forceinline__ uint32_t f2tf32(float f) {
    uint32_t r;
    asm("cvt.rna.tf32.f32 %0, %1;" : "=r"(r) : "f"(f));
    return r;
}

// .cg: bypass L1 (no reuse in gathered input; keep L1 bandwidth for LDSM/RED)
#define CP_ASYNC16(dst, src, sz) \
    asm volatile("cp.async.cg.shared.global [%0], [%1], 16, %2;" \
                 :: "r"(dst), "l"(src), "r"(sz) : "memory")

#define LDSM_X4(r0, r1, r2, r3, addr) \
    asm volatile("ldmatrix.sync.aligned.m8n8.x4.shared.b16 {%0,%1,%2,%3}, [%4];" \
                 : "=r"(r0), "=r"(r1), "=r"(r2), "=r"(r3) : "r"(addr))

#define MMA_TF32(c, a0, a1, a2, a3, b0, b1) \
    asm volatile("mma.sync.aligned.m16n8k8.row.col.f32.tf32.tf32.f32 " \
                 "{%0,%1,%2,%3}, {%4,%5,%6,%7}, {%8,%9}, {%0,%1,%2,%3};" \
                 : "+f"(c[0]), "+f"(c[1]), "+f"(c[2]), "+f"(c[3]) \
                 : "r"(a0), "r"(a1), "r"(a2), "r"(a3), "r"(b0), "r"(b1))

__global__ void __launch_bounds__(256) init_bias_kernel(
    const float* __restrict__ bias, float* __restrict__ out)
{
    int idx = blockIdx.x * 256 + threadIdx.x;
    if (idx < NPTS * CCH) out[idx] = bias[idx & (CCH - 1)];
}

// swizzled byte offset inside a 256B row: chunk' = k16 ^ (row & 7)
__device__ __forceinline__ uint32_t sw_off(int row, int k16) {
    return (uint32_t)(row * 256 + ((k16 ^ (row & 7)) << 4));
}

__global__ void __launch_bounds__(256) sparse_conv_kernel(
    const float* __restrict__ input,
    const float* __restrict__ kernel,
    const int*   __restrict__ in_map,
    const int*   __restrict__ out_map,
    float*       __restrict__ out)
{
    extern __shared__ __align__(1024) char smem[];
    const uint32_t sb = smem_u32(smem);
    int* mapsB = (int*)(smem + MAPS_OFF);   // 3 bufs x 256 ints (in[128], out[128])

    const int k    = blockIdx.y;
    const int t0   = blockIdx.x * TPB;      // first 128-pair tile of this block
    const int tid  = threadIdx.x;
    const int w    = tid >> 5;
    const int l    = tid & 31;
    const int band = w >> 1;                // 32-row band
    const int half = w & 1;                 // 32-col half

    // ---- prologue: W LDG + maps(tile0) LDG issued together ----
    float4 wv[4];
    {
        const float4* Wg = (const float4*)(kernel + k * CCH * CCH);
        #pragma unroll
        for (int s = 0; s < 4; s++) wv[s] = Wg[tid + 256 * s];
    }
    int mIn = -1, mOut = -1;
    if (tid < RPT) {
        int pp = t0 * RPT + tid;
        if (pp < PAIRS) {
            mIn  = in_map [k * PAIRS + pp];
            mOut = out_map[k * PAIRS + pp];
        }
    }

    // W -> padded scratch [i][n] (stride 66); maps tile0 -> buf 0
    {
        float* scratch = (float*)(smem + WS_OFF);
        #pragma unroll
        for (int s = 0; s < 4; s++) {
            int e  = tid + 256 * s;
            int i  = e >> 4;
            int o4 = e & 15;
            float* d = scratch + 66 * i + 4 * o4;
            d[0] = wv[s].x; d[1] = wv[s].y; d[2] = wv[s].z; d[3] = wv[s].w;
        }
    }
    if (tid < RPT) {
        mapsB[tid]       = mIn;
        mapsB[RPT + tid] = mOut;
    }
    __syncthreads();

    // issue gather for tile 0 (maps via LDS), then W transpose -> sB
    #pragma unroll
    for (int s = 0; s < 8; s++) {
        int m   = tid + 256 * s;
        int p   = m >> 4;
        int j16 = m & 15;
        int row = mapsB[p];
        uint32_t dst = sb + SA_OFF + sw_off(p, j16);
        const char* src = (const char*)input
                        + (size_t)(row < 0 ? 0 : row) * 256 + j16 * 16;
        CP_ASYNC16(dst, src, row >= 0 ? 16u : 0u);
    }
    asm volatile("cp.async.commit_group;" ::: "memory");

    {
        float* scratch = (float*)(smem + WS_OFF);
        int n  = tid & 63;
        int ib = (tid >> 6) * 16;
        uint32_t tv[16];
        #pragma unroll
        for (int j = 0; j < 16; j++) tv[j] = f2tf32(scratch[66 * (ib + j) + n]);
        #pragma unroll
        for (int c = 0; c < 4; c++) {
            uint4 q4 = make_uint4(tv[4*c], tv[4*c+1], tv[4*c+2], tv[4*c+3]);
            *(uint4*)(smem + SB_OFF + sw_off(n, (ib >> 2) + c)) = q4;
        }
    }

    // LDG maps for tile 1
    mIn = -1; mOut = -1;
    if (tid < RPT && 1 < TPB) {
        int pp = (t0 + 1) * RPT + tid;
        if (pp < PAIRS) {
            mIn  = in_map [k * PAIRS + pp];
            mOut = out_map[k * PAIRS + pp];
        }
    }

    // GEMM fragment constants
    const int arowB = 32 * band + (((l >> 3) & 1) << 3) + (l & 7);  // + 16*mt
    const int ahi   = l >> 4;
    const int asw   = arowB & 7;
    const int brow  = ((l >> 4) << 3) + (l & 7);                    // + n0
    const int bhi   = (l >> 3) & 1;
    const int bsw   = brow & 7;
    const uint32_t bBase = sb + SB_OFF + brow * 256;
    const int Q = l >> 2;
    const int q = l & 3;

    // ---- hoist ALL B fragments into registers (sB is block-constant) ----
    __syncthreads();                        // sB fully written, block-wide
    uint32_t bf[8][4][2];
    #pragma unroll
    for (int kk = 0; kk < 8; kk++) {
        #pragma unroll
        for (int gl = 0; gl < 2; gl++) {
            int g = 2 * half + gl;
            uint32_t r0, r1, r2, r3;
            uint32_t addr = bBase + g * 4096 + ((((kk << 1) | bhi) ^ bsw) << 4);
            LDSM_X4(r0, r1, r2, r3, addr);
            bf[kk][2 * gl][0] = r0;     bf[kk][2 * gl][1] = r1;
            bf[kk][2 * gl + 1][0] = r2; bf[kk][2 * gl + 1][1] = r3;
        }
    }

    // ---- pipelined tile loop ----
    for (int t = 0; t < TPB; t++) {
        const int cur = t & 1;
        const int mb  = t % 3;
        const int nb  = (t + 1) % 3;

        asm volatile("cp.async.wait_group 0;" ::: "memory");

        // stage maps for tile t+1 (regs loaded last iteration)
        if (t + 1 < TPB && tid < RPT) {
            mapsB[nb * 256 + tid]       = mIn;
            mapsB[nb * 256 + RPT + tid] = mOut;
        }
        __syncthreads();   // sA[cur] ready; maps t+1 visible; sA[cur^1] reads done

        // preload scatter indices for THIS tile (latency hides under GEMM)
        const int* sOutB = mapsB + mb * 256 + RPT;
        int oIdx[2][2];
        #pragma unroll
        for (int mt = 0; mt < 2; mt++)
            #pragma unroll
            for (int h = 0; h < 2; h++)
                oIdx[mt][h] = sOutB[32 * band + 16 * mt + Q + 8 * h];

        // issue gather for tile t+1 into the other buffer
        if (t + 1 < TPB) {
            #pragma unroll
            for (int s = 0; s < 8; s++) {
                int m   = tid + 256 * s;
                int p   = m >> 4;
                int j16 = m & 15;
                int row = mapsB[nb * 256 + p];
                uint32_t dst = sb + SA_OFF + (cur ^ 1) * 32768 + sw_off(p, j16);
                const char* src = (const char*)input
                                + (size_t)(row < 0 ? 0 : row) * 256 + j16 * 16;
                CP_ASYNC16(dst, src, row >= 0 ? 16u : 0u);
            }
            asm volatile("cp.async.commit_group;" ::: "memory");
            // LDG maps for tile t+2
            mIn = -1; mOut = -1;
            if (t + 2 < TPB && tid < RPT) {
                int pp = (t0 + t + 2) * RPT + tid;
                if (pp < PAIRS) {
                    mIn  = in_map [k * PAIRS + pp];
                    mOut = out_map[k * PAIRS + pp];
                }
            }
        }

        // ---- GEMM: warp (band,half) -> rows [32*band,+32) x cols [32*half,+32) ----
        float acc[2][4][4];
        #pragma unroll
        for (int mt = 0; mt < 2; mt++)
            #pragma unroll
            for (int nt = 0; nt < 4; nt++)
                #pragma unroll
                for (int c = 0; c < 4; c++) acc[mt][nt][c] = 0.f;

        const uint32_t aBase = sb + SA_OFF + cur * 32768 + arowB * 256;

        #pragma unroll
        for (int kk = 0; kk < 8; kk++) {
            uint32_t a[2][4];
            #pragma unroll
            for (int mt = 0; mt < 2; mt++) {
                uint32_t addr = aBase + mt * 4096 + ((((kk << 1) | ahi) ^ asw) << 4);
                LDSM_X4(a[mt][0], a[mt][1], a[mt][2], a[mt][3], addr);
            }
            #pragma unroll
            for (int mt = 0; mt < 2; mt++)
                #pragma unroll
                for (int nt = 0; nt < 4; nt++)
                    MMA_TF32(acc[mt][nt], a[mt][0], a[mt][1], a[mt][2], a[mt][3],
                             bf[kk][nt][0], bf[kk][nt][1]);
        }

        // ---- scatter: intra-quad regroup -> each red.v4 touches 8 rows ----
        #pragma unroll
        for (int mt = 0; mt < 2; mt++) {
            #pragma unroll
            for (int h = 0; h < 2; h++) {
                int o = oIdx[mt][h];
                #pragma unroll
                for (int x = 0; x < 2; x++) {
                    float v[4];
                    #pragma unroll
                    for (int j = 0; j < 4; j++) {
                        int par  = j & 1;
                        int srcl = (l & ~3) + 2 * (q & 1) + (j >> 1);
                        float s0 = __shfl_sync(0xffffffffu,
                                               acc[mt][2 * x + 0][2 * h + par], srcl);
                        float s1 = __shfl_sync(0xffffffffu,
                                               acc[mt][2 * x + 1][2 * h + par], srcl);
                        v[j] = (q >> 1) ? s1 : s0;
                    }
                    if (o >= 0)
                        RED_V4(out + o * CCH + 32 * half + 16 * x + 4 * q,
                               v[0], v[1], v[2], v[3]);
                }
            }
        }
    }
}

extern "C" void kernel_launch(void* const* d_in, const int* in_sizes, int n_in,
                              void* d_out, int out_size)
{
    const float* input  = (const float*)d_in[0];
    const float* kern   = (const float*)d_in[1];
    const float* bias   = (const float*)d_in[2];
    const int*   in_map = (const int*)  d_in[3];
    const int*   out_map= (const int*)  d_in[4];
    float* out = (float*)d_out;

    cudaFuncSetAttribute(sparse_conv_kernel,
                         cudaFuncAttributeMaxDynamicSharedMemorySize, SMEM_BYTES);

    init_bias_kernel<<<(NPTS * CCH + 255) / 256, 256>>>(bias, out);

    dim3 grid(GX, KVOL);
    sparse_conv_kernel<<<grid, 256, SMEM_BYTES>>>(input, kern, in_map, out_map, out);
}

// round 15
// speedup vs baseline: 1.7992x; 1.0828x over previous
#include <cuda_runtime.h>
#include <cstdint>

#define NPTS  100000
#define KVOL  27
#define PAIRS 60000
#define CCH   64
#define RPT   128                      // pair rows per tile
#define TPB   11                       // tiles per block (grid 43*27=1161 ~ 3.92 waves of 296)
#define NT128 ((PAIRS + RPT - 1) / RPT)        // 469
#define GX    ((NT128 + TPB - 1) / TPB)        // 43

// smem: sA[2] 128x64 f32-as-tf32 (swizzled 256B rows, 2x32KB) | sB 64x64 tf32
//       (16KB) | W scratch 64x66 f32 (16.9KB) | maps: 3 bufs x (128 in + 128 out)
#define SA_OFF   0
#define SB_OFF   65536
#define WS_OFF   81920
#define MAPS_OFF 98816
#define SMEM_BYTES 101888

#define RED_V4(ptr, x, y, z, w) \
    asm volatile("red.global.add.v4.f32 [%0], {%1,%2,%3,%4};" \
                 :: "l"(ptr), "f"(x), "f"(y), "f"(z), "f"(w) : "memory")

__device__ __forceinline__ uint32_t smem_u32(const void* p) {
    uint32_t a;
    asm("{ .reg .u64 t; cvta.to.shared.u64 t, %1; cvt.u32.u64 %0, t; }"
        : "=r"(a) : "l"(p));
    return a;
}

__device__ __forceinline__ uint32_t f2tf32(float f) {
    uint32_t r;
    asm("cvt.rna.tf32.f32 %0, %1;" : "=r"(r) : "f"(f));
    return r;
}

// .cg: bypass L1 (no reuse in gathered input; keep L1 bandwidth for LDSM/RED)
#define CP_ASYNC16(dst, src, sz) \
    asm volatile("cp.async.cg.shared.global [%0], [%1], 16, %2;" \
                 :: "r"(dst), "l"(src), "r"(sz) : "memory")

#define LDSM_X4(r0, r1, r2, r3, addr) \
    asm volatile("ldmatrix.sync.aligned.m8n8.x4.shared.b16 {%0,%1,%2,%3}, [%4];" \
                 : "=r"(r0), "=r"(r1), "=r"(r2), "=r"(r3) : "r"(addr))

#define MMA_TF32(c, a0, a1, a2, a3, b0, b1) \
    asm volatile("mma.sync.aligned.m16n8k8.row.col.f32.tf32.tf32.f32 " \
                 "{%0,%1,%2,%3}, {%4,%5,%6,%7}, {%8,%9}, {%0,%1,%2,%3};" \
                 : "+f"(c[0]), "+f"(c[1]), "+f"(c[2]), "+f"(c[3]) \
                 : "r"(a0), "r"(a1), "r"(a2), "r"(a3), "r"(b0), "r"(b1))

// vectorized: one float4 per thread, bias row broadcast from registers
__global__ void __launch_bounds__(256) init_bias_kernel(
    const float* __restrict__ bias, float* __restrict__ out)
{
    int idx = blockIdx.x * 256 + threadIdx.x;          // float4 index
    if (idx < NPTS * (CCH / 4)) {
        float4 b = ((const float4*)bias)[idx & (CCH / 4 - 1)];
        ((float4*)out)[idx] = b;
    }
}

// swizzled byte offset inside a 256B row: chunk' = k16 ^ (row & 7)
__device__ __forceinline__ uint32_t sw_off(int row, int k16) {
    return (uint32_t)(row * 256 + ((k16 ^ (row & 7)) << 4));
}

__global__ void __launch_bounds__(256) sparse_conv_kernel(
    const float* __restrict__ input,
    const float* __restrict__ kernel,
    const int*   __restrict__ in_map,
    const int*   __restrict__ out_map,
    float*       __restrict__ out)
{
    extern __shared__ __align__(1024) char smem[];
    const uint32_t sb = smem_u32(smem);
    int* mapsB = (int*)(smem + MAPS_OFF);   // 3 bufs x 256 ints (in[128], out[128])

    const int k    = blockIdx.y;
    const int t0   = blockIdx.x * TPB;      // first 128-pair tile of this block
    const int tid  = threadIdx.x;
    const int w    = tid >> 5;
    const int l    = tid & 31;
    const int band = w >> 1;                // 32-row band
    const int half = w & 1;                 // 32-col half

    // ---- prologue: W LDG + maps(tile0) LDG issued together ----
    float4 wv[4];
    {
        const float4* Wg = (const float4*)(kernel + k * CCH * CCH);
        #pragma unroll
        for (int s = 0; s < 4; s++) wv[s] = Wg[tid + 256 * s];
    }
    int mIn = -1, mOut = -1;
    if (tid < RPT) {
        int pp = t0 * RPT + tid;
        if (pp < PAIRS) {
            mIn  = in_map [k * PAIRS + pp];
            mOut = out_map[k * PAIRS + pp];
        }
    }

    // W -> padded scratch [i][n] (stride 66); maps tile0 -> buf 0
    {
        float* scratch = (float*)(smem + WS_OFF);
        #pragma unroll
        for (int s = 0; s < 4; s++) {
            int e  = tid + 256 * s;
            int i  = e >> 4;
            int o4 = e & 15;
            float* d = scratch + 66 * i + 4 * o4;
            d[0] = wv[s].x; d[1] = wv[s].y; d[2] = wv[s].z; d[3] = wv[s].w;
        }
    }
    if (tid < RPT) {
        mapsB[tid]       = mIn;
        mapsB[RPT + tid] = mOut;
    }
    __syncthreads();

    // issue gather for tile 0 (maps via LDS), then W transpose -> sB
    #pragma unroll
    for (int s = 0; s < 8; s++) {
        int m   = tid + 256 * s;
        int p   = m >> 4;
        int j16 = m & 15;
        int row = mapsB[p];
        uint32_t dst = sb + SA_OFF + sw_off(p, j16);
        const char* src = (const char*)input
                        + (size_t)(row < 0 ? 0 : row) * 256 + j16 * 16;
        CP_ASYNC16(dst, src, row >= 0 ? 16u : 0u);
    }
    asm volatile("cp.async.commit_group;" ::: "memory");

    {
        float* scratch = (float*)(smem + WS_OFF);
        int n  = tid & 63;
        int ib = (tid >> 6) * 16;
        uint32_t tv[16];
        #pragma unroll
        for (int j = 0; j < 16; j++) tv[j] = f2tf32(scratch[66 * (ib + j) + n]);
        #pragma unroll
        for (int c = 0; c < 4; c++) {
            uint4 q4 = make_uint4(tv[4*c], tv[4*c+1], tv[4*c+2], tv[4*c+3]);
            *(uint4*)(smem + SB_OFF + sw_off(n, (ib >> 2) + c)) = q4;
        }
    }

    // LDG maps for tile 1
    mIn = -1; mOut = -1;
    if (tid < RPT && 1 < TPB) {
        int pp = (t0 + 1) * RPT + tid;
        if (pp < PAIRS) {
            mIn  = in_map [k * PAIRS + pp];
            mOut = out_map[k * PAIRS + pp];
        }
    }

    // GEMM fragment constants
    const int arowB = 32 * band + (((l >> 3) & 1) << 3) + (l & 7);  // + 16*mt
    const int ahi   = l >> 4;
    const int asw   = arowB & 7;
    const int brow  = ((l >> 4) << 3) + (l & 7);                    // + n0
    const int bhi   = (l >> 3) & 1;
    const int bsw   = brow & 7;
    const uint32_t bBase = sb + SB_OFF + brow * 256;
    const int Q = l >> 2;
    const int q = l & 3;

    // ---- hoist ALL B fragments into registers (sB is block-constant) ----
    __syncthreads();                        // sB fully written, block-wide
    uint32_t bf[8][4][2];
    #pragma unroll
    for (int kk = 0; kk < 8; kk++) {
        #pragma unroll
        for (int gl = 0; gl < 2; gl++) {
            int g = 2 * half + gl;
            uint32_t r0, r1, r2, r3;
            uint32_t addr = bBase + g * 4096 + ((((kk << 1) | bhi) ^ bsw) << 4);
            LDSM_X4(r0, r1, r2, r3, addr);
            bf[kk][2 * gl][0] = r0;     bf[kk][2 * gl][1] = r1;
            bf[kk][2 * gl + 1][0] = r2; bf[kk][2 * gl + 1][1] = r3;
        }
    }

    // ---- pipelined tile loop ----
    for (int t = 0; t < TPB; t++) {
        const int cur = t & 1;
        const int mb  = t % 3;
        const int nb  = (t + 1) % 3;

        asm volatile("cp.async.wait_group 0;" ::: "memory");

        // stage maps for tile t+1 (regs loaded last iteration)
        if (t + 1 < TPB && tid < RPT) {
            mapsB[nb * 256 + tid]       = mIn;
            mapsB[nb * 256 + RPT + tid] = mOut;
        }
        __syncthreads();   // sA[cur] ready; maps t+1 visible; sA[cur^1] reads done

        // preload scatter indices for THIS tile (latency hides under GEMM)
        const int* sOutB = mapsB + mb * 256 + RPT;
        int oIdx[2][2];
        #pragma unroll
        for (int mt = 0; mt < 2; mt++)
            #pragma unroll
            for (int h = 0; h < 2; h++)
                oIdx[mt][h] = sOutB[32 * band + 16 * mt + Q + 8 * h];

        // issue gather for tile t+1 into the other buffer
        if (t + 1 < TPB) {
            #pragma unroll
            for (int s = 0; s < 8; s++) {
                int m   = tid + 256 * s;
                int p   = m >> 4;
                int j16 = m & 15;
                int row = mapsB[nb * 256 + p];
                uint32_t dst = sb + SA_OFF + (cur ^ 1) * 32768 + sw_off(p, j16);
                const char* src = (const char*)input
                                + (size_t)(row < 0 ? 0 : row) * 256 + j16 * 16;
                CP_ASYNC16(dst, src, row >= 0 ? 16u : 0u);
            }
            asm volatile("cp.async.commit_group;" ::: "memory");
            // LDG maps for tile t+2
            mIn = -1; mOut = -1;
            if (t + 2 < TPB && tid < RPT) {
                int pp = (t0 + t + 2) * RPT + tid;
                if (pp < PAIRS) {
                    mIn  = in_map [k * PAIRS + pp];
                    mOut = out_map[k * PAIRS + pp];
                }
            }
        }

        // ---- GEMM: warp (band,half) -> rows [32*band,+32) x cols [32*half,+32) ----
        float acc[2][4][4];
        #pragma unroll
        for (int mt = 0; mt < 2; mt++)
            #pragma unroll
            for (int nt = 0; nt < 4; nt++)
                #pragma unroll
                for (int c = 0; c < 4; c++) acc[mt][nt][c] = 0.f;

        const uint32_t aBase = sb + SA_OFF + cur * 32768 + arowB * 256;

        #pragma unroll
        for (int kk = 0; kk < 8; kk++) {
            uint32_t a[2][4];
            #pragma unroll
            for (int mt = 0; mt < 2; mt++) {
                uint32_t addr = aBase + mt * 4096 + ((((kk << 1) | ahi) ^ asw) << 4);
                LDSM_X4(a[mt][0], a[mt][1], a[mt][2], a[mt][3], addr);
            }
            #pragma unroll
            for (int mt = 0; mt < 2; mt++)
                #pragma unroll
                for (int nt = 0; nt < 4; nt++)
                    MMA_TF32(acc[mt][nt], a[mt][0], a[mt][1], a[mt][2], a[mt][3],
                             bf[kk][nt][0], bf[kk][nt][1]);
        }

        // ---- scatter: intra-quad regroup -> each red.v4 touches 8 rows ----
        #pragma unroll
        for (int mt = 0; mt < 2; mt++) {
            #pragma unroll
            for (int h = 0; h < 2; h++) {
                int o = oIdx[mt][h];
                #pragma unroll
                for (int x = 0; x < 2; x++) {
                    float v[4];
                    #pragma unroll
                    for (int j = 0; j < 4; j++) {
                        int par  = j & 1;
                        int srcl = (l & ~3) + 2 * (q & 1) + (j >> 1);
                        float s0 = __shfl_sync(0xffffffffu,
                                               acc[mt][2 * x + 0][2 * h + par], srcl);
                        float s1 = __shfl_sync(0xffffffffu,
                                               acc[mt][2 * x + 1][2 * h + par], srcl);
                        v[j] = (q >> 1) ? s1 : s0;
                    }
                    if (o >= 0)
                        RED_V4(out + o * CCH + 32 * half + 16 * x + 4 * q,
                               v[0], v[1], v[2], v[3]);
                }
            }
        }
    }
}

extern "C" void kernel_launch(void* const* d_in, const int* in_sizes, int n_in,
                              void* d_out, int out_size)
{
    const float* input  = (const float*)d_in[0];
    const float* kern   = (const float*)d_in[1];
    const float* bias   = (const float*)d_in[2];
    const int*   in_map = (const int*)  d_in[3];
    const int*   out_map= (const int*)  d_in[4];
    float* out = (float*)d_out;

    cudaFuncSetAttribute(sparse_conv_kernel,
                         cudaFuncAttributeMaxDynamicSharedMemorySize, SMEM_BYTES);

    init_bias_kernel<<<(NPTS * (CCH / 4) + 255) / 256, 256>>>(bias, out);

    dim3 grid(GX, KVOL);
    sparse_conv_kernel<<<grid, 256, SMEM_BYTES>>>(input, kern, in_map, out_map, out);
}